// round 16
// baseline (speedup 1.0000x reference)
#include <cuda_runtime.h>
#include <cuda_fp16.h>
#include <math.h>
#include <stdint.h>

// Problem constants
#define B_   2
#define T_   1024
#define D_   4096
#define NQ   32
#define NKV  8
#define HD   128
#define MTOT (B_ * T_)      // 2048
#define QKV_N 6144          // 4096 q + 1024 k + 1024 v
#define K_OFF 4096
#define V_OFF 5120

#define NEG_INF (-INFINITY)
#define PERSIST_GRID 296     // 148 SMs x 2 CTAs

// -------- scratch (device globals; allocation-free) --------
__device__ __align__(256) __half g_qh[(size_t)MTOT * NQ * HD];    // 16 MB
__device__ __align__(256) __half g_kh[(size_t)MTOT * NKV * HD];   //  4 MB
__device__ __align__(256) __half g_vh[(size_t)MTOT * NKV * HD];   //  4 MB
__device__ __align__(256) __half g_oh[(size_t)MTOT * NQ * HD];    // 16 MB
__device__ __align__(256) __half g_xh[(size_t)MTOT * D_];         // 16 MB
__device__ __align__(256) __half g_wqkvh[(size_t)D_ * QKV_N];     // 48 MB ([k][n] natural)
__device__ __align__(256) __half g_woh[(size_t)NQ * HD * D_];     // 32 MB ([nh][d] natural)
__device__ int g_start[B_];
__device__ int g_first[B_];

// ============================================================
// helpers
// ============================================================
__device__ __forceinline__ uint32_t smem_u32(const void* p) {
    uint32_t a;
    asm("{ .reg .u64 t; cvta.to.shared.u64 t, %1; cvt.u32.u64 %0, t; }" : "=r"(a) : "l"(p));
    return a;
}
__device__ __forceinline__ uint32_t h2_as_u32(__half2 h) {
    return *reinterpret_cast<uint32_t*>(&h);
}

#define CP_ASYNC16(saddr, gptr) \
    asm volatile("cp.async.cg.shared.global [%0], [%1], 16;" :: "r"(saddr), "l"(gptr) : "memory")
#define CP_COMMIT() asm volatile("cp.async.commit_group;" ::: "memory")
#define CP_WAIT1()  asm volatile("cp.async.wait_group 1;" ::: "memory")
#define CP_WAIT0()  asm volatile("cp.async.wait_group 0;" ::: "memory")

#define LDSM4(r0, r1, r2, r3, addr) \
    asm volatile("ldmatrix.sync.aligned.m8n8.x4.shared.b16 {%0,%1,%2,%3}, [%4];" \
        : "=r"(r0), "=r"(r1), "=r"(r2), "=r"(r3) : "r"(addr))
#define LDSM4T(r0, r1, r2, r3, addr) \
    asm volatile("ldmatrix.sync.aligned.m8n8.x4.trans.shared.b16 {%0,%1,%2,%3}, [%4];" \
        : "=r"(r0), "=r"(r1), "=r"(r2), "=r"(r3) : "r"(addr))

__device__ __forceinline__ void mma_f16(float c[4],
                                        uint32_t a0, uint32_t a1, uint32_t a2, uint32_t a3,
                                        uint32_t b0, uint32_t b1) {
    asm volatile(
        "mma.sync.aligned.m16n8k16.row.col.f32.f16.f16.f32 "
        "{%0,%1,%2,%3}, {%4,%5,%6,%7}, {%8,%9}, {%0,%1,%2,%3};"
        : "+f"(c[0]), "+f"(c[1]), "+f"(c[2]), "+f"(c[3])
        : "r"(a0), "r"(a1), "r"(a2), "r"(a3), "r"(b0), "r"(b1));
}

// ============================================================
// 1) segment scan
// ============================================================
__global__ void startfirst_kernel(const int* __restrict__ seg) {
    int b = blockIdx.x;
    const int* s = seg + (size_t)b * T_;
    __shared__ int sh_min, sh_max, sh_first;
    if (threadIdx.x == 0) { sh_min = T_; sh_max = INT_MIN; sh_first = T_; }
    __syncthreads();
    int lmin = T_, lmax = INT_MIN;
    for (int t = threadIdx.x; t < T_; t += blockDim.x) {
        int v = s[t];
        if (v != 0 && t < lmin) lmin = t;
        if (v > lmax) lmax = v;
    }
    atomicMin(&sh_min, lmin);
    atomicMax(&sh_max, lmax);
    __syncthreads();
    int mx = sh_max;
    int lfirst = T_;
    for (int t = threadIdx.x; t < T_; t += blockDim.x)
        if (s[t] == mx && t < lfirst) lfirst = t;
    atomicMin(&sh_first, lfirst);
    __syncthreads();
    if (threadIdx.x == 0) { g_start[b] = sh_min; g_first[b] = sh_first; }
}

// ============================================================
// 2) merged x + wqkv conversion (blockIdx-range dispatch, 2x unroll)
// ============================================================
#define GX_BLOCKS 4096     // (MTOT*D_/8)/256
#define GW_BLOCKS 12288    // (D_*QKV_N/8)/256

__global__ void convert_xw_kernel(const float4* __restrict__ x,
                                  const float4* __restrict__ wq,
                                  const float4* __restrict__ wk,
                                  const float4* __restrict__ wv,
                                  __half2* __restrict__ xh,
                                  __half2* __restrict__ wqkvh) {
    if (blockIdx.x < GX_BLOCKS) {
        int i = 2 * (blockIdx.x * 256 + threadIdx.x);
        float4 v0 = x[i], v1 = x[i + 1];
        xh[2 * i]     = __floats2half2_rn(v0.x, v0.y);
        xh[2 * i + 1] = __floats2half2_rn(v0.z, v0.w);
        xh[2 * i + 2] = __floats2half2_rn(v1.x, v1.y);
        xh[2 * i + 3] = __floats2half2_rn(v1.z, v1.w);
    } else {
        int i0 = 2 * ((blockIdx.x - GX_BLOCKS) * 256 + threadIdx.x);
#pragma unroll
        for (int u = 0; u < 2; ++u) {
            int i = i0 + u;
            int row = i / (QKV_N / 4);
            int c4  = i % (QKV_N / 4);
            float4 v;
            if (c4 < 1024)       v = wq[(size_t)row * 1024 + c4];
            else if (c4 < 1280)  v = wk[(size_t)row * 256 + (c4 - 1024)];
            else                 v = wv[(size_t)row * 256 + (c4 - 1280)];
            wqkvh[2 * i]     = __floats2half2_rn(v.x, v.y);
            wqkvh[2 * i + 1] = __floats2half2_rn(v.z, v.w);
        }
    }
}

// ============================================================
// 3) fp16 mma.sync GEMM, persistent-CTA tile loop.
//    FUSE=true: QKV epilogue + trailing wo f32->f16 convert (grid-stride).
// ============================================================
#define A_STRIDE_B 144
#define B_STRIDE_B 272
#define A_TILE_BYTES (128 * A_STRIDE_B)
#define B_TILE_BYTES (64 * B_STRIDE_B)
#define STAGE_BYTES (A_TILE_BYTES + B_TILE_BYTES)
#define GSTAGES 3
#define GEMM_SMEM (GSTAGES * STAGE_BYTES)

template <bool FUSE>
__global__ __launch_bounds__(128, 2)
void gemm_f16_kernel(const __half* __restrict__ A, const __half* __restrict__ Bn,
                     float* __restrict__ C, int N, int K, int ntiles, int grid_nx,
                     const float* __restrict__ qscale, const float* __restrict__ kscale,
                     const int* __restrict__ seg,
                     const float4* __restrict__ cvt_src, __half2* __restrict__ cvt_dst,
                     size_t cvt_n4) {
    extern __shared__ char smem[];
    const uint32_t sb = smem_u32(smem);
    const int tid  = threadIdx.x;
    const int wid  = tid >> 5;
    const int lane = tid & 31;
    const int g    = lane >> 2;
    const int r    = lane & 3;
    const int wm   = (wid >> 1) * 64;
    const int wn   = (wid & 1) * 64;
    const int lrow = lane & 15;
    const int lk8  = (lane >> 4) * 8;
    const int mrow = lane >> 3;
    const int mi   = lane & 7;
    const int KS = K >> 6;

    for (int tile = blockIdx.x; tile < ntiles; tile += gridDim.x) {
        const int bx = tile % grid_nx;
        const int by = tile / grid_nx;
        const int row0 = by * 128;
        const int col0 = bx * 128;

        float acc[4][8][4];
#pragma unroll
        for (int a = 0; a < 4; ++a)
#pragma unroll
            for (int b = 0; b < 8; ++b)
#pragma unroll
                for (int c = 0; c < 4; ++c) acc[a][b][c] = 0.f;

        auto load_stage = [&](int st, int k0) {
            uint32_t abase = sb + st * STAGE_BYTES;
            uint32_t bbase = abase + A_TILE_BYTES;
#pragma unroll
            for (int j = 0; j < 8; ++j) {
                int f  = tid + 128 * j;
                int rr = f >> 3, cc = f & 7;
                CP_ASYNC16(abase + rr * A_STRIDE_B + cc * 16,
                           A + (size_t)(row0 + rr) * K + k0 + cc * 8);
            }
#pragma unroll
            for (int j = 0; j < 8; ++j) {
                int f  = tid + 128 * j;
                int rr = f >> 4, cc = f & 15;
                CP_ASYNC16(bbase + rr * B_STRIDE_B + cc * 16,
                           Bn + (size_t)(k0 + rr) * N + col0 + cc * 8);
            }
        };

        auto compute_stage = [&](int st) {
            uint32_t abase = sb + st * STAGE_BYTES;
            uint32_t bbase = abase + A_TILE_BYTES;
#pragma unroll
            for (int ks = 0; ks < 4; ++ks) {
                const int key = ks * 16 + (mrow & 1) * 8 + mi;
                uint32_t br[4][4];
#pragma unroll
                for (int ntp = 0; ntp < 4; ++ntp) {
                    uint32_t addr = bbase + (uint32_t)key * B_STRIDE_B
                                  + (uint32_t)(wn + ntp * 16 + (mrow >> 1) * 8) * 2;
                    LDSM4T(br[ntp][0], br[ntp][1], br[ntp][2], br[ntp][3], addr);
                }
                const int kb = ks * 16 + lk8;
#pragma unroll
                for (int mt = 0; mt < 4; ++mt) {
                    uint32_t a0, a1, a2, a3;
                    uint32_t addr = abase + (uint32_t)(wm + mt * 16 + lrow) * A_STRIDE_B + kb * 2;
                    LDSM4(a0, a1, a2, a3, addr);
#pragma unroll
                    for (int ntp = 0; ntp < 4; ++ntp) {
                        mma_f16(acc[mt][2 * ntp],     a0, a1, a2, a3, br[ntp][0], br[ntp][1]);
                        mma_f16(acc[mt][2 * ntp + 1], a0, a1, a2, a3, br[ntp][2], br[ntp][3]);
                    }
                }
            }
        };

        load_stage(0, 0);   CP_COMMIT();
        load_stage(1, 64);  CP_COMMIT();

        for (int i = 0; i < KS; ++i) {
            CP_WAIT1();
            __syncthreads();
            if (i + 2 < KS) load_stage((i + 2) % 3, (i + 2) << 6);
            CP_COMMIT();
            compute_stage(i % 3);
        }

        if (!FUSE) {
#pragma unroll
            for (int mt = 0; mt < 4; ++mt) {
                int mrowg = row0 + wm + mt * 16;
#pragma unroll
                for (int nt = 0; nt < 8; ++nt) {
                    int ncol = col0 + wn + nt * 8 + 2 * r;
                    *reinterpret_cast<float2*>(&C[(size_t)(mrowg + g) * N + ncol]) =
                        make_float2(acc[mt][nt][0], acc[mt][nt][1]);
                    *reinterpret_cast<float2*>(&C[(size_t)(mrowg + g + 8) * N + ncol]) =
                        make_float2(acc[mt][nt][2], acc[mt][nt][3]);
                }
            }
            __syncthreads();
            continue;
        }

        // ---- fused QKV epilogue ----
        CP_WAIT0();
        __syncthreads();
        float* S = reinterpret_cast<float*>(smem);
#pragma unroll
        for (int mt = 0; mt < 4; ++mt) {
            int mr = wm + mt * 16 + g;
#pragma unroll
            for (int nt = 0; nt < 8; ++nt) {
                int nc = wn + nt * 8 + 2 * r;
                S[mr * 130 + nc]           = acc[mt][nt][0];
                S[mr * 130 + nc + 1]       = acc[mt][nt][1];
                S[(mr + 8) * 130 + nc]     = acc[mt][nt][2];
                S[(mr + 8) * 130 + nc + 1] = acc[mt][nt][3];
            }
        }
        __syncthreads();

        const int head = bx;
        const int row  = tid;
        const int bt   = row0 + row;
        const int b    = bt >> 10;
        const int t    = bt & (T_ - 1);
        const float* v = S + row * 130;

        if (head >= 40) {
            __half* dst = g_vh + ((size_t)bt * NKV + (head - 40)) * HD;
#pragma unroll 16
            for (int c2 = 0; c2 < 128; c2 += 2)
                *reinterpret_cast<__half2*>(dst + c2) =
                    __floats2half2_rn(v[c2], v[c2 + 1]);
            __syncthreads();
            continue;
        }

        float ss = 0.f;
#pragma unroll 16
        for (int c = 0; c < 128; ++c) ss += v[c] * v[c];
        float rinv = rsqrtf(ss * (1.0f / HD) + 1e-6f);

        int   segv  = seg[bt];
        int   first = g_first[b];
        float pos   = (segv != 0) ? (float)(t - first) : 1073741824.0f;

        const float* sc = (head < NQ) ? qscale : kscale;
        const float  oscale = (head < NQ) ? 0.08838834764831845f : 1.0f;
        __half* dst = (head < NQ)
            ? g_qh + ((size_t)bt * NQ + head) * HD
            : g_kh + ((size_t)bt * NKV + (head - NQ)) * HD;

#pragma unroll 8
        for (int c2 = 0; c2 < 64; c2 += 2) {
            float lo[2], hi[2];
#pragma unroll
            for (int u = 0; u < 2; ++u) {
                int c = c2 + u;
                float invf = exp2f((-2.0f * (float)c / 128.0f) * 19.931568569324174f);
                float ang  = pos * invf;
                float s_ = sinf(ang), c_ = cosf(ang);
                float n_lo = sc[c] * v[c] * rinv;
                float n_hi = sc[c + 64] * v[c + 64] * rinv;
                lo[u] = (n_lo * c_ - n_hi * s_) * oscale;
                hi[u] = (n_hi * c_ + n_lo * s_) * oscale;
            }
            *reinterpret_cast<__half2*>(dst + c2)      = __floats2half2_rn(lo[0], lo[1]);
            *reinterpret_cast<__half2*>(dst + 64 + c2) = __floats2half2_rn(hi[0], hi[1]);
        }
        __syncthreads();
    }

    // ---- trailing convert work (wo f32->f16), rides in the GEMM wave tail ----
    if (FUSE && cvt_src) {
        for (size_t i = (size_t)blockIdx.x * 128 + tid; i < cvt_n4;
             i += (size_t)gridDim.x * 128) {
            float4 v = cvt_src[i];
            cvt_dst[2 * i]     = __floats2half2_rn(v.x, v.y);
            cvt_dst[2 * i + 1] = __floats2half2_rn(v.z, v.w);
        }
    }
}

// ============================================================
// 4) flash attention: BM=64 q x BN=64 k, 4 warps, gmem Q fragments,
//    3 CTAs/SM (R15 config, unchanged)
// ============================================================
#define FA_STRIDE 136
#define FA_TILE_B (64 * FA_STRIDE * 2)       // 17408
#define FA_SMEM (4 * FA_TILE_B)              // 69632

__global__ __launch_bounds__(128, 3)
void fattn_kernel() {
    extern __shared__ char smem[];
    const uint32_t sb = smem_u32(smem);
    const uint32_t kbase0 = sb;
    const uint32_t vbase0 = sb + FA_TILE_B;

    const int tid  = threadIdx.x;
    const int wid  = tid >> 5;
    const int lane = tid & 31;
    const int g    = lane >> 2;
    const int r    = lane & 3;
    const int lrow = lane & 15;
    const int lk8  = (lane >> 4) * 8;
    const int b  = blockIdx.z;
    const int n  = blockIdx.y;
    const int kh = n >> 2;
    const int t0 = blockIdx.x * 64;

    const int start = g_start[b];
    const int s_begin = start & ~63;
    const int ntiles = (t0 + 64 - s_begin) >> 6;

    auto load_kv = [&](int st, int s0) {
        uint32_t kb = kbase0 + st * 2 * FA_TILE_B;
        uint32_t vb = vbase0 + st * 2 * FA_TILE_B;
        const __half* ksrc = g_kh + ((size_t)(b * T_ + s0) * NKV + kh) * HD;
        const __half* vsrc = g_vh + ((size_t)(b * T_ + s0) * NKV + kh) * HD;
#pragma unroll
        for (int j = 0; j < 8; ++j) {
            int f = tid + 128 * j;
            int row = f >> 4, c = f & 15;
            CP_ASYNC16(kb + row * 272 + c * 16, ksrc + (size_t)row * (NKV * HD) + c * 8);
            CP_ASYNC16(vb + row * 272 + c * 16, vsrc + (size_t)row * (NKV * HD) + c * 8);
        }
    };

    if (ntiles > 0) load_kv(0, s_begin);
    CP_COMMIT();

    const int tq0 = t0 + wid * 16 + g;
    const int tq1 = tq0 + 8;

    uint32_t qf[8][4];
    {
        const __half* q0 = g_qh + ((size_t)(b * T_ + tq0) * NQ + n) * HD;
        const __half* q1 = q0 + (size_t)8 * NQ * HD;
#pragma unroll
        for (int kt = 0; kt < 8; ++kt) {
            int col = kt * 16 + 2 * r;
            qf[kt][0] = *reinterpret_cast<const uint32_t*>(q0 + col);
            qf[kt][1] = *reinterpret_cast<const uint32_t*>(q1 + col);
            qf[kt][2] = *reinterpret_cast<const uint32_t*>(q0 + col + 8);
            qf[kt][3] = *reinterpret_cast<const uint32_t*>(q1 + col + 8);
        }
    }

    float m0 = NEG_INF, m1 = NEG_INF, l0 = 0.f, l1 = 0.f;
    float o[16][4];
#pragma unroll
    for (int i = 0; i < 16; ++i)
#pragma unroll
        for (int j = 0; j < 4; ++j) o[i][j] = 0.f;

    for (int it = 0; it < ntiles; ++it) {
        const int s0 = s_begin + it * 64;
        if (it + 1 < ntiles) load_kv((it + 1) & 1, s0 + 64);
        CP_COMMIT();
        CP_WAIT1();
        __syncthreads();

        const uint32_t kb = kbase0 + (it & 1) * 2 * FA_TILE_B;
        const uint32_t vb = vbase0 + (it & 1) * 2 * FA_TILE_B;

        if (s0 <= tq1) {
            float sfr[8][4];
#pragma unroll
            for (int i = 0; i < 8; ++i)
#pragma unroll
                for (int j = 0; j < 4; ++j) sfr[i][j] = 0.f;

#pragma unroll
            for (int ks = 0; ks < 8; ++ks) {
                const int kcol = ks * 16 + lk8;
#pragma unroll
                for (int np = 0; np < 4; ++np) {
                    uint32_t b0, b1, b2, b3;
                    uint32_t addr = kb + (uint32_t)(np * 16 + lrow) * 272 + kcol * 2;
                    LDSM4(b0, b1, b2, b3, addr);
                    mma_f16(sfr[2 * np],     qf[ks][0], qf[ks][1], qf[ks][2], qf[ks][3], b0, b2);
                    mma_f16(sfr[2 * np + 1], qf[ks][0], qf[ks][1], qf[ks][2], qf[ks][3], b1, b3);
                }
            }

            float mx0 = NEG_INF, mx1 = NEG_INF;
#pragma unroll
            for (int nt = 0; nt < 8; ++nt) {
#pragma unroll
                for (int c = 0; c < 2; ++c) {
                    int s = s0 + nt * 8 + 2 * r + c;
                    bool vs = (s >= start);
                    float v0 = (vs && s <= tq0) ? sfr[nt][c]     : NEG_INF;
                    float v1 = (vs && s <= tq1) ? sfr[nt][2 + c] : NEG_INF;
                    sfr[nt][c]     = v0;
                    sfr[nt][2 + c] = v1;
                    mx0 = fmaxf(mx0, v0);
                    mx1 = fmaxf(mx1, v1);
                }
            }
            mx0 = fmaxf(mx0, __shfl_xor_sync(0xffffffffu, mx0, 1));
            mx0 = fmaxf(mx0, __shfl_xor_sync(0xffffffffu, mx0, 2));
            mx1 = fmaxf(mx1, __shfl_xor_sync(0xffffffffu, mx1, 1));
            mx1 = fmaxf(mx1, __shfl_xor_sync(0xffffffffu, mx1, 2));

            float mn0 = fmaxf(m0, mx0), mn1 = fmaxf(m1, mx1);
            float mu0 = (mn0 == NEG_INF) ? 0.f : mn0;
            float mu1 = (mn1 == NEG_INF) ? 0.f : mn1;
            float alpha0 = (m0 == NEG_INF) ? ((mn0 == NEG_INF) ? 1.f : 0.f) : __expf(m0 - mn0);
            float alpha1 = (m1 == NEG_INF) ? ((mn1 == NEG_INF) ? 1.f : 0.f) : __expf(m1 - mn1);
            m0 = mn0; m1 = mn1;

            float ps0 = 0.f, ps1 = 0.f;
#pragma unroll
            for (int nt = 0; nt < 8; ++nt) {
#pragma unroll
                for (int c = 0; c < 2; ++c) {
                    float p0 = __expf(sfr[nt][c]     - mu0);
                    float p1 = __expf(sfr[nt][2 + c] - mu1);
                    sfr[nt][c]     = p0;
                    sfr[nt][2 + c] = p1;
                    ps0 += p0; ps1 += p1;
                }
            }
            ps0 += __shfl_xor_sync(0xffffffffu, ps0, 1);
            ps0 += __shfl_xor_sync(0xffffffffu, ps0, 2);
            ps1 += __shfl_xor_sync(0xffffffffu, ps1, 1);
            ps1 += __shfl_xor_sync(0xffffffffu, ps1, 2);
            l0 = l0 * alpha0 + ps0;
            l1 = l1 * alpha1 + ps1;

#pragma unroll
            for (int nt = 0; nt < 16; ++nt) {
                o[nt][0] *= alpha0; o[nt][1] *= alpha0;
                o[nt][2] *= alpha1; o[nt][3] *= alpha1;
            }

#pragma unroll
            for (int kt = 0; kt < 4; ++kt) {
                uint32_t a0 = h2_as_u32(__floats2half2_rn(sfr[2 * kt][0],     sfr[2 * kt][1]));
                uint32_t a1 = h2_as_u32(__floats2half2_rn(sfr[2 * kt][2],     sfr[2 * kt][3]));
                uint32_t a2 = h2_as_u32(__floats2half2_rn(sfr[2 * kt + 1][0], sfr[2 * kt + 1][1]));
                uint32_t a3 = h2_as_u32(__floats2half2_rn(sfr[2 * kt + 1][2], sfr[2 * kt + 1][3]));
                const int mrow = lane >> 3, mi = lane & 7;
                const int key = kt * 16 + (mrow & 1) * 8 + mi;
#pragma unroll
                for (int dp = 0; dp < 8; ++dp) {
                    uint32_t v0, v1, v2, v3;
                    uint32_t addr = vb + (uint32_t)key * 272 + (dp * 16 + (mrow >> 1) * 8) * 2;
                    LDSM4T(v0, v1, v2, v3, addr);
                    mma_f16(o[2 * dp],     a0, a1, a2, a3, v0, v1);
                    mma_f16(o[2 * dp + 1], a0, a1, a2, a3, v2, v3);
                }
            }
        }
        __syncthreads();
    }

    float inv0 = (l0 > 0.f) ? (1.0f / l0) : 0.f;
    float inv1 = (l1 > 0.f) ? (1.0f / l1) : 0.f;
    __half* o0 = g_oh + ((size_t)(b * T_ + tq0) * NQ + n) * HD;
    __half* o1 = g_oh + ((size_t)(b * T_ + tq1) * NQ + n) * HD;
#pragma unroll
    for (int nt = 0; nt < 16; ++nt) {
        int col = nt * 8 + 2 * r;
        *reinterpret_cast<__half2*>(o0 + col) =
            __floats2half2_rn(o[nt][0] * inv0, o[nt][1] * inv0);
        *reinterpret_cast<__half2*>(o1 + col) =
            __floats2half2_rn(o[nt][2] * inv1, o[nt][3] * inv1);
    }
}

// ============================================================
// launch
// ============================================================
extern "C" void kernel_launch(void* const* d_in, const int* in_sizes, int n_in,
                              void* d_out, int out_size) {
    const float* x       = (const float*)d_in[0];
    const float* wq      = (const float*)d_in[1];
    const float* wk      = (const float*)d_in[2];
    const float* wv      = (const float*)d_in[3];
    const float* wo      = (const float*)d_in[4];
    const float* q_scale = (const float*)d_in[5];
    const float* k_scale = (const float*)d_in[6];
    const int*   seg     = (const int*)d_in[9];
    float* out = (float*)d_out;

    __half *pxh, *pwqkvh, *pwoh, *poh;
    cudaGetSymbolAddress((void**)&pxh, g_xh);
    cudaGetSymbolAddress((void**)&pwqkvh, g_wqkvh);
    cudaGetSymbolAddress((void**)&pwoh, g_woh);
    cudaGetSymbolAddress((void**)&poh, g_oh);

    cudaFuncSetAttribute(gemm_f16_kernel<true>, cudaFuncAttributeMaxDynamicSharedMemorySize,
                         GEMM_SMEM);
    cudaFuncSetAttribute(gemm_f16_kernel<false>, cudaFuncAttributeMaxDynamicSharedMemorySize,
                         GEMM_SMEM);
    cudaFuncSetAttribute(fattn_kernel, cudaFuncAttributeMaxDynamicSharedMemorySize,
                         FA_SMEM);

    startfirst_kernel<<<B_, 256>>>(seg);

    // merged x + wqkv f32->f16 conversion
    convert_xw_kernel<<<GX_BLOCKS + GW_BLOCKS, 256>>>(
        (const float4*)x, (const float4*)wq, (const float4*)wk, (const float4*)wv,
        (__half2*)pxh, (__half2*)pwqkvh);

    // fused QKV projection + RMSNorm + RoPE (persistent),
    // wo f32->f16 convert folded into the wave tail
    gemm_f16_kernel<true><<<PERSIST_GRID, 128, GEMM_SMEM>>>(
        pxh, pwqkvh, nullptr, QKV_N, D_, (QKV_N / 128) * (MTOT / 128), QKV_N / 128,
        q_scale, k_scale, seg,
        (const float4*)wo, (__half2*)pwoh, (size_t)NQ * HD * D_ / 4);

    fattn_kernel<<<dim3(T_ / 64, NQ, B_), 128, FA_SMEM>>>();

    // output projection (persistent)
    gemm_f16_kernel<false><<<PERSIST_GRID, 128, GEMM_SMEM>>>(
        poh, pwoh, out, D_, NQ * HD, (D_ / 128) * (MTOT / 128), D_ / 128,
        nullptr, nullptr, nullptr, nullptr, nullptr, 0);
}

// round 17
// speedup vs baseline: 1.0738x; 1.0738x over previous
#include <cuda_runtime.h>
#include <cuda_fp16.h>
#include <math.h>
#include <stdint.h>

// Problem constants
#define B_   2
#define T_   1024
#define D_   4096
#define NQ   32
#define NKV  8
#define HD   128
#define MTOT (B_ * T_)      // 2048
#define QKV_N 6144          // 4096 q + 1024 k + 1024 v
#define K_OFF 4096
#define V_OFF 5120

#define NEG_INF (-INFINITY)
#define PERSIST_GRID 296     // 148 SMs x 2 CTAs

// -------- scratch (device globals; allocation-free) --------
__device__ __align__(256) __half g_qh[(size_t)MTOT * NQ * HD];    // 16 MB
__device__ __align__(256) __half g_kh[(size_t)MTOT * NKV * HD];   //  4 MB
__device__ __align__(256) __half g_vh[(size_t)MTOT * NKV * HD];   //  4 MB
__device__ __align__(256) __half g_oh[(size_t)MTOT * NQ * HD];    // 16 MB
__device__ __align__(256) __half g_xh[(size_t)MTOT * D_];         // 16 MB
__device__ __align__(256) __half g_wqkvh[(size_t)D_ * QKV_N];     // 48 MB ([k][n] natural)
__device__ __align__(256) __half g_woh[(size_t)NQ * HD * D_];     // 32 MB ([nh][d] natural)
__device__ int g_start[B_];
__device__ int g_first[B_];

// ============================================================
// helpers
// ============================================================
__device__ __forceinline__ uint32_t smem_u32(const void* p) {
    uint32_t a;
    asm("{ .reg .u64 t; cvta.to.shared.u64 t, %1; cvt.u32.u64 %0, t; }" : "=r"(a) : "l"(p));
    return a;
}
__device__ __forceinline__ uint32_t h2_as_u32(__half2 h) {
    return *reinterpret_cast<uint32_t*>(&h);
}

#define CP_ASYNC16(saddr, gptr) \
    asm volatile("cp.async.cg.shared.global [%0], [%1], 16;" :: "r"(saddr), "l"(gptr) : "memory")
#define CP_COMMIT() asm volatile("cp.async.commit_group;" ::: "memory")
#define CP_WAIT1()  asm volatile("cp.async.wait_group 1;" ::: "memory")
#define CP_WAIT0()  asm volatile("cp.async.wait_group 0;" ::: "memory")

#define LDSM4(r0, r1, r2, r3, addr) \
    asm volatile("ldmatrix.sync.aligned.m8n8.x4.shared.b16 {%0,%1,%2,%3}, [%4];" \
        : "=r"(r0), "=r"(r1), "=r"(r2), "=r"(r3) : "r"(addr))
#define LDSM4T(r0, r1, r2, r3, addr) \
    asm volatile("ldmatrix.sync.aligned.m8n8.x4.trans.shared.b16 {%0,%1,%2,%3}, [%4];" \
        : "=r"(r0), "=r"(r1), "=r"(r2), "=r"(r3) : "r"(addr))

__device__ __forceinline__ void mma_f16(float c[4],
                                        uint32_t a0, uint32_t a1, uint32_t a2, uint32_t a3,
                                        uint32_t b0, uint32_t b1) {
    asm volatile(
        "mma.sync.aligned.m16n8k16.row.col.f32.f16.f16.f32 "
        "{%0,%1,%2,%3}, {%4,%5,%6,%7}, {%8,%9}, {%0,%1,%2,%3};"
        : "+f"(c[0]), "+f"(c[1]), "+f"(c[2]), "+f"(c[3])
        : "r"(a0), "r"(a1), "r"(a2), "r"(a3), "r"(b0), "r"(b1));
}

// ============================================================
// 1) segment scan
// ============================================================
__global__ void startfirst_kernel(const int* __restrict__ seg) {
    int b = blockIdx.x;
    const int* s = seg + (size_t)b * T_;
    __shared__ int sh_min, sh_max, sh_first;
    if (threadIdx.x == 0) { sh_min = T_; sh_max = INT_MIN; sh_first = T_; }
    __syncthreads();
    int lmin = T_, lmax = INT_MIN;
    for (int t = threadIdx.x; t < T_; t += blockDim.x) {
        int v = s[t];
        if (v != 0 && t < lmin) lmin = t;
        if (v > lmax) lmax = v;
    }
    atomicMin(&sh_min, lmin);
    atomicMax(&sh_max, lmax);
    __syncthreads();
    int mx = sh_max;
    int lfirst = T_;
    for (int t = threadIdx.x; t < T_; t += blockDim.x)
        if (s[t] == mx && t < lfirst) lfirst = t;
    atomicMin(&sh_first, lfirst);
    __syncthreads();
    if (threadIdx.x == 0) { g_start[b] = sh_min; g_first[b] = sh_first; }
}

// ============================================================
// 2) conversions (element-wise, 2x unrolled) — R15 versions
// ============================================================
__global__ void f32_to_f16_kernel(const float4* __restrict__ src, __half2* __restrict__ dst) {
    int i = 2 * (blockIdx.x * blockDim.x + threadIdx.x);
    float4 v0 = src[i], v1 = src[i + 1];
    dst[2 * i]     = __floats2half2_rn(v0.x, v0.y);
    dst[2 * i + 1] = __floats2half2_rn(v0.z, v0.w);
    dst[2 * i + 2] = __floats2half2_rn(v1.x, v1.y);
    dst[2 * i + 3] = __floats2half2_rn(v1.z, v1.w);
}

__global__ void pack_wqkv_f16_kernel(const float4* __restrict__ wq, const float4* __restrict__ wk,
                                     const float4* __restrict__ wv, __half2* __restrict__ dst) {
    int i0 = 2 * (blockIdx.x * blockDim.x + threadIdx.x);
#pragma unroll
    for (int u = 0; u < 2; ++u) {
        int i = i0 + u;
        int row = i / (QKV_N / 4);
        int c4  = i % (QKV_N / 4);
        float4 v;
        if (c4 < 1024)       v = wq[(size_t)row * 1024 + c4];
        else if (c4 < 1280)  v = wk[(size_t)row * 256 + (c4 - 1024)];
        else                 v = wv[(size_t)row * 256 + (c4 - 1280)];
        dst[2 * i]     = __floats2half2_rn(v.x, v.y);
        dst[2 * i + 1] = __floats2half2_rn(v.z, v.w);
    }
}

// ============================================================
// 3) fp16 mma.sync GEMM, persistent-CTA tile loop (R12/R15, unchanged)
// ============================================================
#define A_STRIDE_B 144
#define B_STRIDE_B 272
#define A_TILE_BYTES (128 * A_STRIDE_B)
#define B_TILE_BYTES (64 * B_STRIDE_B)
#define STAGE_BYTES (A_TILE_BYTES + B_TILE_BYTES)
#define GSTAGES 3
#define GEMM_SMEM (GSTAGES * STAGE_BYTES)

template <bool FUSE>
__global__ __launch_bounds__(128, 2)
void gemm_f16_kernel(const __half* __restrict__ A, const __half* __restrict__ Bn,
                     float* __restrict__ C, int N, int K, int ntiles, int grid_nx,
                     const float* __restrict__ qscale, const float* __restrict__ kscale,
                     const int* __restrict__ seg) {
    extern __shared__ char smem[];
    const uint32_t sb = smem_u32(smem);
    const int tid  = threadIdx.x;
    const int wid  = tid >> 5;
    const int lane = tid & 31;
    const int g    = lane >> 2;
    const int r    = lane & 3;
    const int wm   = (wid >> 1) * 64;
    const int wn   = (wid & 1) * 64;
    const int lrow = lane & 15;
    const int lk8  = (lane >> 4) * 8;
    const int mrow = lane >> 3;
    const int mi   = lane & 7;
    const int KS = K >> 6;

    for (int tile = blockIdx.x; tile < ntiles; tile += gridDim.x) {
        const int bx = tile % grid_nx;
        const int by = tile / grid_nx;
        const int row0 = by * 128;
        const int col0 = bx * 128;

        float acc[4][8][4];
#pragma unroll
        for (int a = 0; a < 4; ++a)
#pragma unroll
            for (int b = 0; b < 8; ++b)
#pragma unroll
                for (int c = 0; c < 4; ++c) acc[a][b][c] = 0.f;

        auto load_stage = [&](int st, int k0) {
            uint32_t abase = sb + st * STAGE_BYTES;
            uint32_t bbase = abase + A_TILE_BYTES;
#pragma unroll
            for (int j = 0; j < 8; ++j) {
                int f  = tid + 128 * j;
                int rr = f >> 3, cc = f & 7;
                CP_ASYNC16(abase + rr * A_STRIDE_B + cc * 16,
                           A + (size_t)(row0 + rr) * K + k0 + cc * 8);
            }
#pragma unroll
            for (int j = 0; j < 8; ++j) {
                int f  = tid + 128 * j;
                int rr = f >> 4, cc = f & 15;
                CP_ASYNC16(bbase + rr * B_STRIDE_B + cc * 16,
                           Bn + (size_t)(k0 + rr) * N + col0 + cc * 8);
            }
        };

        auto compute_stage = [&](int st) {
            uint32_t abase = sb + st * STAGE_BYTES;
            uint32_t bbase = abase + A_TILE_BYTES;
#pragma unroll
            for (int ks = 0; ks < 4; ++ks) {
                const int key = ks * 16 + (mrow & 1) * 8 + mi;
                uint32_t br[4][4];
#pragma unroll
                for (int ntp = 0; ntp < 4; ++ntp) {
                    uint32_t addr = bbase + (uint32_t)key * B_STRIDE_B
                                  + (uint32_t)(wn + ntp * 16 + (mrow >> 1) * 8) * 2;
                    LDSM4T(br[ntp][0], br[ntp][1], br[ntp][2], br[ntp][3], addr);
                }
                const int kb = ks * 16 + lk8;
#pragma unroll
                for (int mt = 0; mt < 4; ++mt) {
                    uint32_t a0, a1, a2, a3;
                    uint32_t addr = abase + (uint32_t)(wm + mt * 16 + lrow) * A_STRIDE_B + kb * 2;
                    LDSM4(a0, a1, a2, a3, addr);
#pragma unroll
                    for (int ntp = 0; ntp < 4; ++ntp) {
                        mma_f16(acc[mt][2 * ntp],     a0, a1, a2, a3, br[ntp][0], br[ntp][1]);
                        mma_f16(acc[mt][2 * ntp + 1], a0, a1, a2, a3, br[ntp][2], br[ntp][3]);
                    }
                }
            }
        };

        load_stage(0, 0);   CP_COMMIT();
        load_stage(1, 64);  CP_COMMIT();

        for (int i = 0; i < KS; ++i) {
            CP_WAIT1();
            __syncthreads();
            if (i + 2 < KS) load_stage((i + 2) % 3, (i + 2) << 6);
            CP_COMMIT();
            compute_stage(i % 3);
        }

        if (!FUSE) {
#pragma unroll
            for (int mt = 0; mt < 4; ++mt) {
                int mrowg = row0 + wm + mt * 16;
#pragma unroll
                for (int nt = 0; nt < 8; ++nt) {
                    int ncol = col0 + wn + nt * 8 + 2 * r;
                    *reinterpret_cast<float2*>(&C[(size_t)(mrowg + g) * N + ncol]) =
                        make_float2(acc[mt][nt][0], acc[mt][nt][1]);
                    *reinterpret_cast<float2*>(&C[(size_t)(mrowg + g + 8) * N + ncol]) =
                        make_float2(acc[mt][nt][2], acc[mt][nt][3]);
                }
            }
            __syncthreads();
            continue;
        }

        // ---- fused QKV epilogue ----
        CP_WAIT0();
        __syncthreads();
        float* S = reinterpret_cast<float*>(smem);
#pragma unroll
        for (int mt = 0; mt < 4; ++mt) {
            int mr = wm + mt * 16 + g;
#pragma unroll
            for (int nt = 0; nt < 8; ++nt) {
                int nc = wn + nt * 8 + 2 * r;
                S[mr * 130 + nc]           = acc[mt][nt][0];
                S[mr * 130 + nc + 1]       = acc[mt][nt][1];
                S[(mr + 8) * 130 + nc]     = acc[mt][nt][2];
                S[(mr + 8) * 130 + nc + 1] = acc[mt][nt][3];
            }
        }
        __syncthreads();

        const int head = bx;
        const int row  = tid;
        const int bt   = row0 + row;
        const int b    = bt >> 10;
        const int t    = bt & (T_ - 1);
        const float* v = S + row * 130;

        if (head >= 40) {
            __half* dst = g_vh + ((size_t)bt * NKV + (head - 40)) * HD;
#pragma unroll 16
            for (int c2 = 0; c2 < 128; c2 += 2)
                *reinterpret_cast<__half2*>(dst + c2) =
                    __floats2half2_rn(v[c2], v[c2 + 1]);
            __syncthreads();
            continue;
        }

        float ss = 0.f;
#pragma unroll 16
        for (int c = 0; c < 128; ++c) ss += v[c] * v[c];
        float rinv = rsqrtf(ss * (1.0f / HD) + 1e-6f);

        int   segv  = seg[bt];
        int   first = g_first[b];
        float pos   = (segv != 0) ? (float)(t - first) : 1073741824.0f;

        const float* sc = (head < NQ) ? qscale : kscale;
        const float  oscale = (head < NQ) ? 0.08838834764831845f : 1.0f;
        __half* dst = (head < NQ)
            ? g_qh + ((size_t)bt * NQ + head) * HD
            : g_kh + ((size_t)bt * NKV + (head - NQ)) * HD;

#pragma unroll 8
        for (int c2 = 0; c2 < 64; c2 += 2) {
            float lo[2], hi[2];
#pragma unroll
            for (int u = 0; u < 2; ++u) {
                int c = c2 + u;
                float invf = exp2f((-2.0f * (float)c / 128.0f) * 19.931568569324174f);
                float ang  = pos * invf;
                float s_ = sinf(ang), c_ = cosf(ang);
                float n_lo = sc[c] * v[c] * rinv;
                float n_hi = sc[c + 64] * v[c + 64] * rinv;
                lo[u] = (n_lo * c_ - n_hi * s_) * oscale;
                hi[u] = (n_hi * c_ + n_lo * s_) * oscale;
            }
            *reinterpret_cast<__half2*>(dst + c2)      = __floats2half2_rn(lo[0], lo[1]);
            *reinterpret_cast<__half2*>(dst + 64 + c2) = __floats2half2_rn(hi[0], hi[1]);
        }
        __syncthreads();
    }
}

// ============================================================
// 4) flash attention: BM=64, 4 warps, gmem Q fragments, 3 CTAs/SM.
//    Heaviest blocks (largest t0 => most KV tiles) scheduled FIRST.
// ============================================================
#define FA_STRIDE 136
#define FA_TILE_B (64 * FA_STRIDE * 2)       // 17408
#define FA_SMEM (4 * FA_TILE_B)              // 69632

__global__ __launch_bounds__(128, 3)
void fattn_kernel() {
    extern __shared__ char smem[];
    const uint32_t sb = smem_u32(smem);
    const uint32_t kbase0 = sb;
    const uint32_t vbase0 = sb + FA_TILE_B;

    const int tid  = threadIdx.x;
    const int wid  = tid >> 5;
    const int lane = tid & 31;
    const int g    = lane >> 2;
    const int r    = lane & 3;
    const int lrow = lane & 15;
    const int lk8  = (lane >> 4) * 8;
    const int b  = blockIdx.z;
    const int n  = blockIdx.y;
    const int kh = n >> 2;
    // heaviest-first: block 0 handles the LAST (longest-causal-span) q tile
    const int t0 = (gridDim.x - 1 - blockIdx.x) * 64;

    const int start = g_start[b];
    const int s_begin = start & ~63;
    const int ntiles = (t0 + 64 - s_begin) >> 6;

    auto load_kv = [&](int st, int s0) {
        uint32_t kb = kbase0 + st * 2 * FA_TILE_B;
        uint32_t vb = vbase0 + st * 2 * FA_TILE_B;
        const __half* ksrc = g_kh + ((size_t)(b * T_ + s0) * NKV + kh) * HD;
        const __half* vsrc = g_vh + ((size_t)(b * T_ + s0) * NKV + kh) * HD;
#pragma unroll
        for (int j = 0; j < 8; ++j) {
            int f = tid + 128 * j;
            int row = f >> 4, c = f & 15;
            CP_ASYNC16(kb + row * 272 + c * 16, ksrc + (size_t)row * (NKV * HD) + c * 8);
            CP_ASYNC16(vb + row * 272 + c * 16, vsrc + (size_t)row * (NKV * HD) + c * 8);
        }
    };

    if (ntiles > 0) load_kv(0, s_begin);
    CP_COMMIT();

    const int tq0 = t0 + wid * 16 + g;
    const int tq1 = tq0 + 8;

    uint32_t qf[8][4];
    {
        const __half* q0 = g_qh + ((size_t)(b * T_ + tq0) * NQ + n) * HD;
        const __half* q1 = q0 + (size_t)8 * NQ * HD;
#pragma unroll
        for (int kt = 0; kt < 8; ++kt) {
            int col = kt * 16 + 2 * r;
            qf[kt][0] = *reinterpret_cast<const uint32_t*>(q0 + col);
            qf[kt][1] = *reinterpret_cast<const uint32_t*>(q1 + col);
            qf[kt][2] = *reinterpret_cast<const uint32_t*>(q0 + col + 8);
            qf[kt][3] = *reinterpret_cast<const uint32_t*>(q1 + col + 8);
        }
    }

    float m0 = NEG_INF, m1 = NEG_INF, l0 = 0.f, l1 = 0.f;
    float o[16][4];
#pragma unroll
    for (int i = 0; i < 16; ++i)
#pragma unroll
        for (int j = 0; j < 4; ++j) o[i][j] = 0.f;

    for (int it = 0; it < ntiles; ++it) {
        const int s0 = s_begin + it * 64;
        if (it + 1 < ntiles) load_kv((it + 1) & 1, s0 + 64);
        CP_COMMIT();
        CP_WAIT1();
        __syncthreads();

        const uint32_t kb = kbase0 + (it & 1) * 2 * FA_TILE_B;
        const uint32_t vb = vbase0 + (it & 1) * 2 * FA_TILE_B;

        if (s0 <= tq1) {
            float sfr[8][4];
#pragma unroll
            for (int i = 0; i < 8; ++i)
#pragma unroll
                for (int j = 0; j < 4; ++j) sfr[i][j] = 0.f;

#pragma unroll
            for (int ks = 0; ks < 8; ++ks) {
                const int kcol = ks * 16 + lk8;
#pragma unroll
                for (int np = 0; np < 4; ++np) {
                    uint32_t b0, b1, b2, b3;
                    uint32_t addr = kb + (uint32_t)(np * 16 + lrow) * 272 + kcol * 2;
                    LDSM4(b0, b1, b2, b3, addr);
                    mma_f16(sfr[2 * np],     qf[ks][0], qf[ks][1], qf[ks][2], qf[ks][3], b0, b2);
                    mma_f16(sfr[2 * np + 1], qf[ks][0], qf[ks][1], qf[ks][2], qf[ks][3], b1, b3);
                }
            }

            float mx0 = NEG_INF, mx1 = NEG_INF;
#pragma unroll
            for (int nt = 0; nt < 8; ++nt) {
#pragma unroll
                for (int c = 0; c < 2; ++c) {
                    int s = s0 + nt * 8 + 2 * r + c;
                    bool vs = (s >= start);
                    float v0 = (vs && s <= tq0) ? sfr[nt][c]     : NEG_INF;
                    float v1 = (vs && s <= tq1) ? sfr[nt][2 + c] : NEG_INF;
                    sfr[nt][c]     = v0;
                    sfr[nt][2 + c] = v1;
                    mx0 = fmaxf(mx0, v0);
                    mx1 = fmaxf(mx1, v1);
                }
            }
            mx0 = fmaxf(mx0, __shfl_xor_sync(0xffffffffu, mx0, 1));
            mx0 = fmaxf(mx0, __shfl_xor_sync(0xffffffffu, mx0, 2));
            mx1 = fmaxf(mx1, __shfl_xor_sync(0xffffffffu, mx1, 1));
            mx1 = fmaxf(mx1, __shfl_xor_sync(0xffffffffu, mx1, 2));

            float mn0 = fmaxf(m0, mx0), mn1 = fmaxf(m1, mx1);
            float mu0 = (mn0 == NEG_INF) ? 0.f : mn0;
            float mu1 = (mn1 == NEG_INF) ? 0.f : mn1;
            float alpha0 = (m0 == NEG_INF) ? ((mn0 == NEG_INF) ? 1.f : 0.f) : __expf(m0 - mn0);
            float alpha1 = (m1 == NEG_INF) ? ((mn1 == NEG_INF) ? 1.f : 0.f) : __expf(m1 - mn1);
            m0 = mn0; m1 = mn1;

            float ps0 = 0.f, ps1 = 0.f;
#pragma unroll
            for (int nt = 0; nt < 8; ++nt) {
#pragma unroll
                for (int c = 0; c < 2; ++c) {
                    float p0 = __expf(sfr[nt][c]     - mu0);
                    float p1 = __expf(sfr[nt][2 + c] - mu1);
                    sfr[nt][c]     = p0;
                    sfr[nt][2 + c] = p1;
                    ps0 += p0; ps1 += p1;
                }
            }
            ps0 += __shfl_xor_sync(0xffffffffu, ps0, 1);
            ps0 += __shfl_xor_sync(0xffffffffu, ps0, 2);
            ps1 += __shfl_xor_sync(0xffffffffu, ps1, 1);
            ps1 += __shfl_xor_sync(0xffffffffu, ps1, 2);
            l0 = l0 * alpha0 + ps0;
            l1 = l1 * alpha1 + ps1;

#pragma unroll
            for (int nt = 0; nt < 16; ++nt) {
                o[nt][0] *= alpha0; o[nt][1] *= alpha0;
                o[nt][2] *= alpha1; o[nt][3] *= alpha1;
            }

#pragma unroll
            for (int kt = 0; kt < 4; ++kt) {
                uint32_t a0 = h2_as_u32(__floats2half2_rn(sfr[2 * kt][0],     sfr[2 * kt][1]));
                uint32_t a1 = h2_as_u32(__floats2half2_rn(sfr[2 * kt][2],     sfr[2 * kt][3]));
                uint32_t a2 = h2_as_u32(__floats2half2_rn(sfr[2 * kt + 1][0], sfr[2 * kt + 1][1]));
                uint32_t a3 = h2_as_u32(__floats2half2_rn(sfr[2 * kt + 1][2], sfr[2 * kt + 1][3]));
                const int mrow = lane >> 3, mi = lane & 7;
                const int key = kt * 16 + (mrow & 1) * 8 + mi;
#pragma unroll
                for (int dp = 0; dp < 8; ++dp) {
                    uint32_t v0, v1, v2, v3;
                    uint32_t addr = vb + (uint32_t)key * 272 + (dp * 16 + (mrow >> 1) * 8) * 2;
                    LDSM4T(v0, v1, v2, v3, addr);
                    mma_f16(o[2 * dp],     a0, a1, a2, a3, v0, v1);
                    mma_f16(o[2 * dp + 1], a0, a1, a2, a3, v2, v3);
                }
            }
        }
        __syncthreads();
    }

    float inv0 = (l0 > 0.f) ? (1.0f / l0) : 0.f;
    float inv1 = (l1 > 0.f) ? (1.0f / l1) : 0.f;
    __half* o0 = g_oh + ((size_t)(b * T_ + tq0) * NQ + n) * HD;
    __half* o1 = g_oh + ((size_t)(b * T_ + tq1) * NQ + n) * HD;
#pragma unroll
    for (int nt = 0; nt < 16; ++nt) {
        int col = nt * 8 + 2 * r;
        *reinterpret_cast<__half2*>(o0 + col) =
            __floats2half2_rn(o[nt][0] * inv0, o[nt][1] * inv0);
        *reinterpret_cast<__half2*>(o1 + col) =
            __floats2half2_rn(o[nt][2] * inv1, o[nt][3] * inv1);
    }
}

// ============================================================
// launch
// ============================================================
extern "C" void kernel_launch(void* const* d_in, const int* in_sizes, int n_in,
                              void* d_out, int out_size) {
    const float* x       = (const float*)d_in[0];
    const float* wq      = (const float*)d_in[1];
    const float* wk      = (const float*)d_in[2];
    const float* wv      = (const float*)d_in[3];
    const float* wo      = (const float*)d_in[4];
    const float* q_scale = (const float*)d_in[5];
    const float* k_scale = (const float*)d_in[6];
    const int*   seg     = (const int*)d_in[9];
    float* out = (float*)d_out;

    __half *pxh, *pwqkvh, *pwoh, *poh;
    cudaGetSymbolAddress((void**)&pxh, g_xh);
    cudaGetSymbolAddress((void**)&pwqkvh, g_wqkvh);
    cudaGetSymbolAddress((void**)&pwoh, g_woh);
    cudaGetSymbolAddress((void**)&poh, g_oh);

    cudaFuncSetAttribute(gemm_f16_kernel<true>, cudaFuncAttributeMaxDynamicSharedMemorySize,
                         GEMM_SMEM);
    cudaFuncSetAttribute(gemm_f16_kernel<false>, cudaFuncAttributeMaxDynamicSharedMemorySize,
                         GEMM_SMEM);
    cudaFuncSetAttribute(fattn_kernel, cudaFuncAttributeMaxDynamicSharedMemorySize,
                         FA_SMEM);

    startfirst_kernel<<<B_, 256>>>(seg);
    f32_to_f16_kernel<<<(MTOT * D_ / 8) / 256, 256>>>(
        (const float4*)x, (__half2*)pxh);
    pack_wqkv_f16_kernel<<<((size_t)D_ * QKV_N / 8) / 256, 256>>>(
        (const float4*)wq, (const float4*)wk, (const float4*)wv,
        (__half2*)pwqkvh);
    f32_to_f16_kernel<<<((size_t)NQ * HD * D_ / 8) / 256, 256>>>(
        (const float4*)wo, (__half2*)pwoh);

    // fused QKV projection + RMSNorm + RoPE (persistent)
    gemm_f16_kernel<true><<<PERSIST_GRID, 128, GEMM_SMEM>>>(
        pxh, pwqkvh, nullptr, QKV_N, D_, (QKV_N / 128) * (MTOT / 128), QKV_N / 128,
        q_scale, k_scale, seg);

    fattn_kernel<<<dim3(T_ / 64, NQ, B_), 128, FA_SMEM>>>();

    // output projection (persistent)
    gemm_f16_kernel<false><<<PERSIST_GRID, 128, GEMM_SMEM>>>(
        poh, pwoh, out, D_, NQ * HD, (D_ / 128) * (MTOT / 128), D_ / 128,
        nullptr, nullptr, nullptr);
}